// round 17
// speedup vs baseline: 3.7080x; 1.0288x over previous
#include <cuda_runtime.h>
#include <cuda_bf16.h>
#include <cuda_fp16.h>
#include <math.h>
#include <stdint.h>

#define BB   32
#define LL   256
#define LP   257
#define PDIM 164
#define KPX  192
#define DD   240
#define KPD  256
#define HH   16
#define DKH  15
#define DKP  16
#define HID  480
#define KPH  512
#define NQKV 720
#define NPQKV 768
#define NPD  256
#define NPH  512
#define NBLK 6
#define NCLS 250
#define NTOK  (BB*LP)
#define NTOK0 (BB*LL)
#define ATT_SCALE 0.25819888974716115f
#define ATT_SCALE_L2E 0.3725024089534673f   /* ATT_SCALE * log2(e) */

typedef __nv_bfloat16 bf16;
typedef __half hf;

// ---- fp32 scratch ----
__device__ float g_h   [NTOK*DD];
__device__ float g_y2  [NTOK0*DD];
__device__ float g_t1f [NTOK0*HID];
__device__ float g_qkvh[3*BB*HH*LP*DKP];   // head-major q/k/v (pads zero-init)
__device__ float g_mask[NTOK];
__device__ float g_pool[BB*DD];
__device__ float g_bqkv[NBLK*NQKV];

// ---- fp16 hi/lo activations ----
__device__ hf g_xphi[NTOK0*KPX], g_xplo[NTOK0*KPX];
__device__ hf g_t1hi[NTOK0*KPH], g_t1lo[NTOK0*KPH];
__device__ hf g_yhi [NTOK*KPD],  g_ylo [NTOK*KPD];
__device__ hf g_ohi [NTOK*KPD],  g_olo [NTOK*KPD];
__device__ hf g_fhi [NTOK*KPH],  g_flo [NTOK*KPH];

// ---- fp16 weights, [N][K] transposed, zero-padded ----
__device__ hf g_eW1h[512*KPX];
__device__ hf g_eW2h[NPD*KPH];
__device__ hf g_wqkvw[NBLK*NPQKV*KPD];
__device__ hf g_woh [NBLK*NPD*KPD];
__device__ hf g_w1h [NBLK*NPH*KPD];
__device__ hf g_w2h [NBLK*NPD*KPH];

// ---------------------------------------------------------------------------
__device__ __forceinline__ void hsplit(float x, hf& h, hf& l) {
    h = __float2half_rn(x);
    l = __float2half_rn(x - __half2float(h));
}
__device__ __forceinline__ void bf16split(float x, bf16& h, bf16& l) {
    h = __float2bfloat16(x);
    l = __float2bfloat16(x - __bfloat162float(h));
}
__device__ __forceinline__ uint32_t s2u(const void* p) {
    return (uint32_t)__cvta_generic_to_shared(p);
}
__device__ __forceinline__ uint32_t swz(uint32_t o) { return o ^ ((o >> 3) & 0x70); }
__device__ __forceinline__ void cp16(uint32_t dst, const void* src) {
    asm volatile("cp.async.cg.shared.global [%0], [%1], 16;" :: "r"(dst), "l"(src));
}
__device__ __forceinline__ void ldsm4(uint32_t r[4], uint32_t addr) {
    asm volatile("ldmatrix.sync.aligned.m8n8.x4.shared.b16 {%0,%1,%2,%3}, [%4];"
                 : "=r"(r[0]), "=r"(r[1]), "=r"(r[2]), "=r"(r[3]) : "r"(addr));
}
__device__ __forceinline__ void mma_f16(float c[4], const uint32_t a[4],
                                        uint32_t b0, uint32_t b1) {
    asm volatile(
        "mma.sync.aligned.m16n8k16.row.col.f32.f16.f16.f32 "
        "{%0,%1,%2,%3}, {%4,%5,%6,%7}, {%8,%9}, {%0,%1,%2,%3};"
        : "+f"(c[0]), "+f"(c[1]), "+f"(c[2]), "+f"(c[3])
        : "r"(a[0]), "r"(a[1]), "r"(a[2]), "r"(a[3]), "r"(b0), "r"(b1));
}
__device__ __forceinline__ void mma_bf16(float c[4], const uint32_t a[4],
                                         uint32_t b0, uint32_t b1) {
    asm volatile(
        "mma.sync.aligned.m16n8k16.row.col.f32.bf16.bf16.f32 "
        "{%0,%1,%2,%3}, {%4,%5,%6,%7}, {%8,%9}, {%0,%1,%2,%3};"
        : "+f"(c[0]), "+f"(c[1]), "+f"(c[2]), "+f"(c[3])
        : "r"(a[0]), "r"(a[1]), "r"(a[2]), "r"(a[3]), "r"(b0), "r"(b1));
}
__device__ __forceinline__ uint32_t pack_bf2(bf16 lo, bf16 hi) {
    __nv_bfloat162 t; t.x = lo; t.y = hi;
    return *(uint32_t*)&t;
}

// smem stage: AH 16K | AL 16K | BH 8K = 40K; two stages = 80K
#define OFS_AL 16384
#define OFS_BH 32768
#define STG    40960
#define GEMM_SMEM (2*STG)

// ---------------------------------------------------------------------------
// fp16 2-pass mma GEMM (single barrier per k-stage).
// ---------------------------------------------------------------------------
template<int EPI>
__global__ __launch_bounds__(256, 2) void mma_gemm(
    const hf* __restrict__ Ahi, const hf* __restrict__ Alo,
    const hf* __restrict__ W,
    const float* __restrict__ bias, const float* __restrict__ Rres,
    float* __restrict__ C, hf* __restrict__ Chi, hf* __restrict__ Clo,
    int M, int Nout, int KP, int SOUT)
{
    extern __shared__ char smem[];
    const uint32_t sb = s2u(smem);
    const int tid = threadIdx.x, lane = tid & 31, warp = tid >> 5;
    const int wm = warp >> 1, wn = warp & 1;
    const int bm = blockIdx.y * 128, bn = blockIdx.x * 64;

    float c[2][4][4];
    #pragma unroll
    for (int i = 0; i < 2; i++)
        #pragma unroll
        for (int j = 0; j < 4; j++)
            #pragma unroll
            for (int r = 0; r < 4; r++) c[i][j][r] = 0.f;

    auto load_stage = [&](int s, int ko) {
        const uint32_t base = sb + s * STG;
        #pragma unroll
        for (int i = 0; i < 4; i++) {
            int idx = tid + i * 256;
            int r = idx >> 3, c8 = idx & 7;
            uint32_t so = swz((uint32_t)(r * 128 + c8 * 16));
            int gm = bm + r; if (gm >= M) gm = M - 1;
            long ao = (long)gm * KP + ko + c8 * 8;
            cp16(base + so,          Ahi + ao);
            cp16(base + OFS_AL + so, Alo + ao);
        }
        #pragma unroll
        for (int i = 0; i < 2; i++) {
            int idx = tid + i * 256;
            int r = idx >> 3, c8 = idx & 7;
            uint32_t so = swz((uint32_t)(r * 128 + c8 * 16));
            long bo = (long)(bn + r) * KP + ko + c8 * 8;
            cp16(base + OFS_BH + so, W + bo);
        }
        asm volatile("cp.async.commit_group;");
    };

    const int nst = KP >> 6;
    load_stage(0, 0);

    const int a_lrow = lane & 15;
    const int a_cofs = (lane >> 4) * 16;
    const int b_lrow = (lane & 7) + ((lane >> 4) << 3);
    const int b_cofs = ((lane >> 3) & 1) * 16;

    for (int t = 0; t < nst; t++) {
        asm volatile("cp.async.wait_group 0;");
        __syncthreads();   // visibility of loads(t) + orders compute(t-1) before loads(t+1)
        if (t + 1 < nst) load_stage((t + 1) & 1, (t + 1) * 64);

        const uint32_t base = sb + (t & 1) * STG;
        #pragma unroll
        for (int ks = 0; ks < 4; ks++) {
            const int colb = ks * 32;
            uint32_t aH[2][4], aL[2][4];
            #pragma unroll
            for (int ma = 0; ma < 2; ma++) {
                int row = wm * 32 + ma * 16 + a_lrow;
                uint32_t off = swz((uint32_t)(row * 128 + colb + a_cofs));
                ldsm4(aH[ma], base + off);
                ldsm4(aL[ma], base + OFS_AL + off);
            }
            uint32_t bH[4][2];
            #pragma unroll
            for (int ntp = 0; ntp < 2; ntp++) {
                int row = wn * 32 + ntp * 16 + b_lrow;
                uint32_t off = swz((uint32_t)(row * 128 + colb + b_cofs));
                uint32_t r4[4];
                ldsm4(r4, base + OFS_BH + off);
                bH[2*ntp][0] = r4[0]; bH[2*ntp][1] = r4[1];
                bH[2*ntp+1][0] = r4[2]; bH[2*ntp+1][1] = r4[3];
            }
            #pragma unroll
            for (int na = 0; na < 4; na++)
                #pragma unroll
                for (int ma = 0; ma < 2; ma++)
                    mma_f16(c[ma][na], aH[ma], bH[na][0], bH[na][1]);
            #pragma unroll
            for (int na = 0; na < 4; na++)
                #pragma unroll
                for (int ma = 0; ma < 2; ma++)
                    mma_f16(c[ma][na], aL[ma], bH[na][0], bH[na][1]);
        }
    }

    const int lq = lane >> 2, lr = lane & 3;
    #pragma unroll
    for (int ma = 0; ma < 2; ma++) {
        #pragma unroll
        for (int na = 0; na < 4; na++) {
            int row0 = bm + wm * 32 + ma * 16 + lq;
            int col0 = bn + wn * 32 + na * 8 + lr * 2;
            #pragma unroll
            for (int half = 0; half < 2; half++) {
                int gm = row0 + half * 8;
                if (gm >= M) continue;
                #pragma unroll
                for (int jj = 0; jj < 2; jj++) {
                    int gn = col0 + jj;
                    float val = c[ma][na][half * 2 + jj];
                    if (EPI == 0) {
                        if (gn < Nout) C[(long)gm * Nout + gn] = val + bias[gn];
                    } else if (EPI == 1) {
                        if (gn < SOUT) {
                            long off = (long)gm * SOUT + gn;
                            float v = (gn < Nout) ? fmaxf(val + bias[gn], 0.f) : 0.f;
                            hf hb, lb; hsplit(v, hb, lb);
                            Chi[off] = hb; Clo[off] = lb;
                        }
                    } else if (EPI == 2) {
                        if (gn < Nout) {
                            long off = (long)gm * Nout + gn;
                            C[off] = val + bias[gn] + Rres[off];
                        }
                    } else {  // EPI == 3: head-major qkv store
                        if (gn < Nout) {
                            int b = gm / LP, l = gm % LP;
                            int sel = gn / DD, rem = gn % DD;
                            int head = rem / DKH, d = rem % DKH;
                            long dst = ((((long)sel * BB + b) * HH + head) * LP + l) * DKP + d;
                            C[dst] = val + bias[gn];
                        }
                    }
                }
            }
        }
    }
}

// ---------------------------------------------------------------------------
__device__ __forceinline__ float warp_red_sum(float v) {
    #pragma unroll
    for (int o = 16; o > 0; o >>= 1) v += __shfl_xor_sync(0xffffffffu, v, o);
    return v;
}
__device__ __forceinline__ float warp_red_max(float v) {
    #pragma unroll
    for (int o = 16; o > 0; o >>= 1)
        v = fmaxf(v, __shfl_xor_sync(0xffffffffu, v, o));
    return v;
}

// ---------------------------------------------------------------------------
template<int RELU>
__global__ __launch_bounds__(256) void ln_split_w(
    const float* __restrict__ X, const float* __restrict__ g,
    const float* __restrict__ bta, hf* __restrict__ Yhi, hf* __restrict__ Ylo,
    int nrows, int D, int SP)
{
    const int warp = threadIdx.x >> 5, lane = threadIdx.x & 31;
    const long row = (long)blockIdx.x * 8 + warp;
    if (row >= nrows) return;
    const float* x = X + row * D;

    float vals[16];
    float s = 0.f;
    #pragma unroll
    for (int k = 0; k < 16; k++) {
        int d = lane + k * 32;
        vals[k] = (d < D) ? x[d] : 0.f;
        s += vals[k];
    }
    s = warp_red_sum(s);
    const float mean = s / (float)D;
    float v2 = 0.f;
    #pragma unroll
    for (int k = 0; k < 16; k++) {
        int d = lane + k * 32;
        if (d < D) { float t = vals[k] - mean; v2 += t * t; }
    }
    v2 = warp_red_sum(v2);
    const float inv = rsqrtf(v2 / (float)D + 1e-5f);

    #pragma unroll
    for (int k = 0; k < 16; k++) {
        int d = lane + k * 32;
        if (d < SP) {
            float vv = 0.f;
            if (d < D) {
                vv = (vals[k] - mean) * inv * g[d] + bta[d];
                if (RELU) vv = fmaxf(vv, 0.f);
            }
            hf hb, lb; hsplit(vv, hb, lb);
            Yhi[row * SP + d] = hb; Ylo[row * SP + d] = lb;
        }
    }
}

__global__ __launch_bounds__(256) void ln_embed(
    const float* __restrict__ X, const float* __restrict__ g,
    const float* __restrict__ bta, const float* __restrict__ pos,
    const float* __restrict__ cls, float* __restrict__ h)
{
    const int warp = threadIdx.x >> 5, lane = threadIdx.x & 31;
    const int NB0 = NTOK0 / 8;
    if (blockIdx.x < NB0) {
        const long row = (long)blockIdx.x * 8 + warp;
        const int b = (int)(row / LL), l = (int)(row % LL);
        const float* x = X + row * DD;
        float vals[8];
        float s = 0.f;
        #pragma unroll
        for (int k = 0; k < 8; k++) {
            int d = lane + k * 32;
            vals[k] = (d < DD) ? x[d] : 0.f;
            s += vals[k];
        }
        s = warp_red_sum(s);
        const float mean = s / (float)DD;
        float v2 = 0.f;
        #pragma unroll
        for (int k = 0; k < 8; k++) {
            int d = lane + k * 32;
            if (d < DD) { float t = vals[k] - mean; v2 += t * t; }
        }
        v2 = warp_red_sum(v2);
        const float inv = rsqrtf(v2 / (float)DD + 1e-5f);
        long ho = ((long)b * LP + l + 1) * DD;
        #pragma unroll
        for (int k = 0; k < 8; k++) {
            int d = lane + k * 32;
            if (d < DD) {
                float vv = fmaxf((vals[k] - mean) * inv * g[d] + bta[d], 0.f);
                h[ho + d] = vv + pos[(long)l * DD + d];
            }
        }
    } else {
        int b = (blockIdx.x - NB0) * 8 + warp;
        if (b < BB) {
            long ho = (long)b * LP * DD;
            #pragma unroll
            for (int k = 0; k < 8; k++) {
                int d = lane + k * 32;
                if (d < DD) h[ho + d] = cls[d];
            }
        }
    }
}

__global__ __launch_bounds__(256) void mask_kernel(
    const float* __restrict__ x, float* __restrict__ msk)
{
    const int warp = threadIdx.x >> 5, lane = threadIdx.x & 31;
    const int t = blockIdx.x * 8 + warp;
    if (t >= NTOK) return;
    const int b = t / LP, l = t % LP;
    if (l == 0) { if (lane == 0) msk[t] = 0.f; return; }
    const float* xr = x + ((long)b * LL + (l - 1)) * PDIM;
    float m = -3.4e38f;
    #pragma unroll
    for (int k = 0; k < 6; k++) {
        int d = lane + k * 32;
        if (d < PDIM) m = fmaxf(m, xr[d]);
    }
    m = warp_red_max(m);
    if (lane == 0) msk[t] = (m == 0.0f) ? 1.f : 0.f;
}

// zero o pad columns 240..255 (run once; attn never touches them)
__global__ void pad_o_kernel(hf* __restrict__ ohi, hf* __restrict__ olo)
{
    int i = blockIdx.x * blockDim.x + threadIdx.x;
    if (i >= NTOK * 16) return;
    long off = (long)(i >> 4) * KPD + 240 + (i & 15);
    ohi[off] = __float2half(0.f);
    olo[off] = __float2half(0.f);
}

// ---------------------------------------------------------------------------
// Tensor-core attention, K/V staged ONCE per (head,batch); 5 q-tiles looped
// in-kernel. Q single bf16 (score path is noise-tolerant); P hi/lo, V hi/lo.
// ---------------------------------------------------------------------------
#define QT   64
#define KCH  272
#define VSTR 272
__global__ __launch_bounds__(128) void attn_tc(
    const float* __restrict__ qkvh, const float* __restrict__ msk,
    hf* __restrict__ ohi, hf* __restrict__ olo)
{
    __shared__ bf16 Qb[QT][16];
    __shared__ bf16 Kb[KCH][16];
    __shared__ bf16 Vth[16][VSTR], Vtl[16][VSTR];
    __shared__ float Msf[KCH];
    const int hd = blockIdx.x, b = blockIdx.y;
    const int tid = threadIdx.x, warp = tid >> 5, lane = tid & 31;
    const long qbase = ((long)b * HH + hd) * LP * DKP;
    const long kbase = ((long)(BB + b) * HH + hd) * LP * DKP;
    const long vbase = ((long)(2 * BB + b) * HH + hd) * LP * DKP;

    for (int i = tid; i < KCH * 16; i += 128) {
        int k = i >> 4, d = i & 15;
        float kv = (k < LP) ? qkvh[kbase + k * DKP + d] : 0.f;
        Kb[k][d] = __float2bfloat16(kv);
        float vv = (k < LP) ? qkvh[vbase + k * DKP + d] : 0.f;
        bf16 hb, lb; bf16split(vv, hb, lb);
        Vth[d][k] = hb; Vtl[d][k] = lb;
    }
    for (int i = tid; i < KCH; i += 128)
        Msf[i] = (i < LP) ? ((msk[b * LP + i] != 0.f) ? 0.f : 1.f) : 0.f;

    const int lq = lane >> 2, lr = lane & 3;
    const uint32_t sK  = s2u(&Kb[0][0]);
    const uint32_t sVh = s2u(&Vth[0][0]);
    const uint32_t sVl = s2u(&Vtl[0][0]);
    const uint32_t qoffA = (uint32_t)((warp * 16 + (lane & 15)) * 32 + (lane >> 4) * 16);
    const uint32_t koffB = (uint32_t)(((lane & 7) + ((lane >> 4) << 3)) * 32
                                     + ((lane >> 3) & 1) * 16);
    const uint32_t voffB = (uint32_t)(((lane & 7) + ((lane >> 4) << 3)) * (VSTR * 2)
                                     + ((lane >> 3) & 1) * 16);

    for (int qt = 0; qt < 5; qt++) {
        __syncthreads();   // protect Qb from previous tile's readers; 1st iter: orders K/V/M staging too
        for (int i = tid; i < QT * 16; i += 128) {
            int r = i >> 4, d = i & 15;
            int q = qt * QT + r;
            float v = (q < LP) ? qkvh[qbase + q * DKP + d] * ATT_SCALE_L2E : 0.f;
            Qb[r][d] = __float2bfloat16(v);
        }
        __syncthreads();

        uint32_t aQ[4];
        ldsm4(aQ, s2u(&Qb[0][0]) + qoffA);

        float co[2][4];
        #pragma unroll
        for (int i = 0; i < 2; i++)
            #pragma unroll
            for (int j = 0; j < 4; j++) co[i][j] = 0.f;
        float sum0 = 0.f, sum1 = 0.f;

        for (int kc = 0; kc < KCH; kc += 16) {
            uint32_t kb4[4];
            ldsm4(kb4, sK + (uint32_t)kc * 32 + koffB);
            float cs0[4] = {0.f, 0.f, 0.f, 0.f}, cs1[4] = {0.f, 0.f, 0.f, 0.f};
            mma_bf16(cs0, aQ, kb4[0], kb4[1]);
            mma_bf16(cs1, aQ, kb4[2], kb4[3]);

            float m00 = Msf[kc + 2 * lr],     m01 = Msf[kc + 2 * lr + 1];
            float m10 = Msf[kc + 8 + 2 * lr], m11 = Msf[kc + 8 + 2 * lr + 1];
            float p00 = exp2f(cs0[0]) * m00, p01 = exp2f(cs0[1]) * m01;
            float p02 = exp2f(cs0[2]) * m00, p03 = exp2f(cs0[3]) * m01;
            float p10 = exp2f(cs1[0]) * m10, p11 = exp2f(cs1[1]) * m11;
            float p12 = exp2f(cs1[2]) * m10, p13 = exp2f(cs1[3]) * m11;
            sum0 += p00 + p01 + p10 + p11;
            sum1 += p02 + p03 + p12 + p13;

            bf16 h0,l0,h1,l1,h2,l2,h3,l3;
            uint32_t aPh[4], aPl[4];
            bf16split(p00,h0,l0); bf16split(p01,h1,l1);
            aPh[0] = pack_bf2(h0,h1); aPl[0] = pack_bf2(l0,l1);
            bf16split(p02,h2,l2); bf16split(p03,h3,l3);
            aPh[1] = pack_bf2(h2,h3); aPl[1] = pack_bf2(l2,l3);
            bf16split(p10,h0,l0); bf16split(p11,h1,l1);
            aPh[2] = pack_bf2(h0,h1); aPl[2] = pack_bf2(l0,l1);
            bf16split(p12,h2,l2); bf16split(p13,h3,l3);
            aPh[3] = pack_bf2(h2,h3); aPl[3] = pack_bf2(l2,l3);

            uint32_t vh4[4], vl4[4];
            ldsm4(vh4, sVh + (uint32_t)kc * 2 + voffB);
            ldsm4(vl4, sVl + (uint32_t)kc * 2 + voffB);
            mma_bf16(co[0], aPh, vh4[0], vh4[1]);
            mma_bf16(co[1], aPh, vh4[2], vh4[3]);
            mma_bf16(co[0], aPl, vh4[0], vh4[1]);
            mma_bf16(co[1], aPl, vh4[2], vh4[3]);
            mma_bf16(co[0], aPh, vl4[0], vl4[1]);
            mma_bf16(co[1], aPh, vl4[2], vl4[3]);
        }

        sum0 += __shfl_xor_sync(0xffffffffu, sum0, 1);
        sum0 += __shfl_xor_sync(0xffffffffu, sum0, 2);
        sum1 += __shfl_xor_sync(0xffffffffu, sum1, 1);
        sum1 += __shfl_xor_sync(0xffffffffu, sum1, 2);
        const float inv0 = 1.f / sum0, inv1 = 1.f / sum1;

        const int q0 = qt * QT + warp * 16 + lq;
        const int q1 = q0 + 8;
        #pragma unroll
        for (int nt = 0; nt < 2; nt++) {
            int d0 = nt * 8 + 2 * lr;
            if (q0 < LP) {
                long ro = ((long)b * LP + q0) * KPD + hd * DKH;
                float v0 = co[nt][0] * inv0;
                hf hb, lb; hsplit(v0, hb, lb);
                ohi[ro + d0] = hb; olo[ro + d0] = lb;
                if (d0 + 1 < 15) {
                    float v1 = co[nt][1] * inv0;
                    hsplit(v1, hb, lb);
                    ohi[ro + d0 + 1] = hb; olo[ro + d0 + 1] = lb;
                }
            }
            if (q1 < LP) {
                long ro = ((long)b * LP + q1) * KPD + hd * DKH;
                float v0 = co[nt][2] * inv1;
                hf hb, lb; hsplit(v0, hb, lb);
                ohi[ro + d0] = hb; olo[ro + d0] = lb;
                if (d0 + 1 < 15) {
                    float v1 = co[nt][3] * inv1;
                    hsplit(v1, hb, lb);
                    ohi[ro + d0 + 1] = hb; olo[ro + d0 + 1] = lb;
                }
            }
        }
    }
}

// ---------------------------------------------------------------------------
__global__ __launch_bounds__(256) void pool_kernel(
    const float* __restrict__ h, const float* __restrict__ msk,
    float* __restrict__ pooled)
{
    __shared__ float Msm[LP];
    __shared__ float cntS;
    const int b = blockIdx.x, tid = threadIdx.x;
    for (int l = tid; l < LP; l += 256) Msm[l] = 1.f - msk[b * LP + l];
    __syncthreads();
    if (tid == 0) {
        float c = 0.f;
        for (int l = 0; l < LP; l++) c += Msm[l];
        cntS = c;
    }
    __syncthreads();
    const float invc = 1.0f / cntS;
    if (tid < DD) {
        float acc = 0.f;
        for (int l = 0; l < LP; l++)
            acc += Msm[l] * h[((long)b * LP + l) * DD + tid];
        pooled[b * DD + tid] = acc * invc;
    }
}

__global__ void logits_kernel(const float* __restrict__ pooled, const float* __restrict__ W,
                              const float* __restrict__ bias, float* __restrict__ out)
{
    __shared__ float p[DD];
    const int b = blockIdx.x, tid = threadIdx.x;
    for (int d = tid; d < DD; d += 256) p[d] = pooled[b * DD + d];
    __syncthreads();
    for (int c = tid; c < NCLS; c += 256) {
        float acc = bias[c];
        for (int d = 0; d < DD; d++) acc += p[d] * W[d * NCLS + c];
        out[b * NCLS + c] = acc;
    }
}

// ---------------------------------------------------------------------------
__global__ void cvt_pad_x(const float* __restrict__ x, hf* __restrict__ hi,
                          hf* __restrict__ lo)
{
    long i = (long)blockIdx.x * blockDim.x + threadIdx.x;
    long n = (long)NTOK0 * KPX;
    for (; i < n; i += (long)gridDim.x * blockDim.x) {
        int col = i % KPX; long row = i / KPX;
        float v = (col < PDIM) ? x[row * PDIM + col] : 0.f;
        hf h, l; hsplit(v, h, l);
        hi[i] = h; lo[i] = l;
    }
}
__global__ void cvt_eW1(const float* __restrict__ w, hf* __restrict__ dst)
{
    long i = (long)blockIdx.x * blockDim.x + threadIdx.x;
    long tot = (long)512 * KPX;
    for (; i < tot; i += (long)gridDim.x * blockDim.x) {
        int k = i % KPX; long nn = i / KPX;
        float v = (nn < HID && k < PDIM) ? w[(long)k * HID + nn] : 0.f;
        dst[i] = __float2half_rn(v);
    }
}
__global__ void cvt_eW2(const float* __restrict__ w, hf* __restrict__ dst)
{
    long i = (long)blockIdx.x * blockDim.x + threadIdx.x;
    long tot = (long)NPD * KPH;
    for (; i < tot; i += (long)gridDim.x * blockDim.x) {
        int k = i % KPH; long nn = i / KPH;
        float v = (nn < DD && k < HID) ? w[(long)k * DD + nn] : 0.f;
        dst[i] = __float2half_rn(v);
    }
}
__global__ void cvt_qkvw(const float* __restrict__ Wq, const float* __restrict__ Wk,
                         const float* __restrict__ Wv, hf* __restrict__ dst)
{
    long i = (long)blockIdx.x * blockDim.x + threadIdx.x;
    long tot = (long)NBLK * NPQKV * KPD;
    for (; i < tot; i += (long)gridDim.x * blockDim.x) {
        int k = i % KPD; long rem = i / KPD;
        int nn = rem % NPQKV; int layer = rem / NPQKV;
        float v = 0.f;
        if (nn < NQKV && k < DD) {
            int sel = nn / DD, cc = nn % DD;
            const float* W = sel == 0 ? Wq : (sel == 1 ? Wk : Wv);
            v = W[((long)layer * DD + k) * DD + cc];
        }
        dst[i] = __float2half_rn(v);
    }
}
__global__ void fuse_qkv_b(const float* __restrict__ bq, const float* __restrict__ bk,
                           const float* __restrict__ bv, float* __restrict__ out)
{
    int i = blockIdx.x * blockDim.x + threadIdx.x;
    if (i >= NBLK * NQKV) return;
    int c = i % NQKV, layer = i / NQKV;
    int sel = c / DD, cc = c % DD;
    const float* B = sel == 0 ? bq : (sel == 1 ? bk : bv);
    out[i] = B[layer * DD + cc];
}
__global__ void cvt_wo(const float* __restrict__ w, hf* __restrict__ dst)
{
    long i = (long)blockIdx.x * blockDim.x + threadIdx.x;
    long tot = (long)NBLK * NPD * KPD;
    for (; i < tot; i += (long)gridDim.x * blockDim.x) {
        int k = i % KPD; long rem = i / KPD;
        int nn = rem % NPD; int layer = rem / NPD;
        float v = (nn < DD && k < DD) ? w[((long)layer * DD + k) * DD + nn] : 0.f;
        dst[i] = __float2half_rn(v);
    }
}
__global__ void cvt_w1(const float* __restrict__ w, hf* __restrict__ dst)
{
    long i = (long)blockIdx.x * blockDim.x + threadIdx.x;
    long tot = (long)NBLK * NPH * KPD;
    for (; i < tot; i += (long)gridDim.x * blockDim.x) {
        int k = i % KPD; long rem = i / KPD;
        int nn = rem % NPH; int layer = rem / NPH;
        float v = (nn < HID && k < DD) ? w[((long)layer * DD + k) * HID + nn] : 0.f;
        dst[i] = __float2half_rn(v);
    }
}
__global__ void cvt_w2(const float* __restrict__ w, hf* __restrict__ dst)
{
    long i = (long)blockIdx.x * blockDim.x + threadIdx.x;
    long tot = (long)NBLK * NPD * KPH;
    for (; i < tot; i += (long)gridDim.x * blockDim.x) {
        int k = i % KPH; long rem = i / KPH;
        int nn = rem % NPD; int layer = rem / NPD;
        float v = (nn < DD && k < HID) ? w[((long)layer * HID + k) * DD + nn] : 0.f;
        dst[i] = __float2half_rn(v);
    }
}

// ---------------------------------------------------------------------------
extern "C" void kernel_launch(void* const* d_in, const int* in_sizes, int n_in,
                              void* d_out, int out_size)
{
    const float* x    = (const float*)d_in[0];
    const float* pos  = (const float*)d_in[1];
    const float* cls  = (const float*)d_in[2];
    const float* eW1  = (const float*)d_in[3];
    const float* eb1  = (const float*)d_in[4];
    const float* eg1  = (const float*)d_in[5];
    const float* ebn1 = (const float*)d_in[6];
    const float* eW2  = (const float*)d_in[7];
    const float* eb2  = (const float*)d_in[8];
    const float* eg2  = (const float*)d_in[9];
    const float* ebn2 = (const float*)d_in[10];
    const float* ln1g = (const float*)d_in[11];
    const float* ln1b = (const float*)d_in[12];
    const float* Wq   = (const float*)d_in[13];
    const float* bq   = (const float*)d_in[14];
    const float* Wk   = (const float*)d_in[15];
    const float* bk   = (const float*)d_in[16];
    const float* Wv   = (const float*)d_in[17];
    const float* bv   = (const float*)d_in[18];
    const float* Wo   = (const float*)d_in[19];
    const float* bo   = (const float*)d_in[20];
    const float* ln2g = (const float*)d_in[21];
    const float* ln2b = (const float*)d_in[22];
    const float* W1   = (const float*)d_in[23];
    const float* b1   = (const float*)d_in[24];
    const float* W2   = (const float*)d_in[25];
    const float* b2   = (const float*)d_in[26];
    const float* logW = (const float*)d_in[27];
    const float* logb = (const float*)d_in[28];
    float* out = (float*)d_out;

    float *h, *y2, *t1f, *qkvh, *msk, *pool, *bqkv;
    hf *xphi,*xplo,*t1hi,*t1lo,*yhi,*ylo,*ohi,*olo,*fhi,*flo;
    hf *eW1h,*eW2h,*wqkvw,*woh,*w1h,*w2h;
    cudaGetSymbolAddress((void**)&h,     g_h);
    cudaGetSymbolAddress((void**)&y2,    g_y2);
    cudaGetSymbolAddress((void**)&t1f,   g_t1f);
    cudaGetSymbolAddress((void**)&qkvh,  g_qkvh);
    cudaGetSymbolAddress((void**)&msk,   g_mask);
    cudaGetSymbolAddress((void**)&pool,  g_pool);
    cudaGetSymbolAddress((void**)&bqkv,  g_bqkv);
    cudaGetSymbolAddress((void**)&xphi,  g_xphi);
    cudaGetSymbolAddress((void**)&xplo,  g_xplo);
    cudaGetSymbolAddress((void**)&t1hi,  g_t1hi);
    cudaGetSymbolAddress((void**)&t1lo,  g_t1lo);
    cudaGetSymbolAddress((void**)&yhi,   g_yhi);
    cudaGetSymbolAddress((void**)&ylo,   g_ylo);
    cudaGetSymbolAddress((void**)&ohi,   g_ohi);
    cudaGetSymbolAddress((void**)&olo,   g_olo);
    cudaGetSymbolAddress((void**)&fhi,   g_fhi);
    cudaGetSymbolAddress((void**)&flo,   g_flo);
    cudaGetSymbolAddress((void**)&eW1h,  g_eW1h);
    cudaGetSymbolAddress((void**)&eW2h,  g_eW2h);
    cudaGetSymbolAddress((void**)&wqkvw, g_wqkvw);
    cudaGetSymbolAddress((void**)&woh,   g_woh);
    cudaGetSymbolAddress((void**)&w1h,   g_w1h);
    cudaGetSymbolAddress((void**)&w2h,   g_w2h);

    cudaFuncSetAttribute(mma_gemm<0>, cudaFuncAttributeMaxDynamicSharedMemorySize, GEMM_SMEM);
    cudaFuncSetAttribute(mma_gemm<1>, cudaFuncAttributeMaxDynamicSharedMemorySize, GEMM_SMEM);
    cudaFuncSetAttribute(mma_gemm<2>, cudaFuncAttributeMaxDynamicSharedMemorySize, GEMM_SMEM);
    cudaFuncSetAttribute(mma_gemm<3>, cudaFuncAttributeMaxDynamicSharedMemorySize, GEMM_SMEM);

    cvt_pad_x<<<1024, 256>>>(x, xphi, xplo);
    cvt_eW1  <<<256, 256>>>(eW1, eW1h);
    cvt_eW2  <<<256, 256>>>(eW2, eW2h);

    // ---- embedding MLP ----
    mma_gemm<0><<<dim3(8, 64), 256, GEMM_SMEM>>>(xphi, xplo, eW1h, eb1,
        nullptr, t1f, nullptr, nullptr, NTOK0, HID, KPX, 0);
    ln_split_w<1><<<NTOK0 / 8, 256>>>(t1f, eg1, ebn1, t1hi, t1lo, NTOK0, HID, KPH);
    mma_gemm<0><<<dim3(4, 64), 256, GEMM_SMEM>>>(t1hi, t1lo, eW2h, eb2,
        nullptr, y2, nullptr, nullptr, NTOK0, DD, KPH, 0);
    ln_embed<<<NTOK0 / 8 + 4, 256>>>(y2, eg2, ebn2, pos, cls, h);

    mask_kernel<<<(NTOK + 7) / 8, 256>>>(x, msk);
    fuse_qkv_b<<<(NBLK * NQKV + 255) / 256, 256>>>(bq, bk, bv, bqkv);
    cvt_qkvw<<<1024, 256>>>(Wq, Wk, Wv, wqkvw);
    cvt_wo  <<<512, 256>>>(Wo, woh);
    cvt_w1  <<<512, 256>>>(W1, w1h);
    cvt_w2  <<<512, 256>>>(W2, w2h);
    pad_o_kernel<<<(NTOK * 16 + 255) / 256, 256>>>(ohi, olo);

    // ---- transformer blocks ----
    for (int i = 0; i < NBLK; i++) {
        ln_split_w<0><<<(NTOK + 7) / 8, 256>>>(h, ln1g + i * DD, ln1b + i * DD,
                                               yhi, ylo, NTOK, DD, KPD);
        mma_gemm<3><<<dim3(12, 65), 256, GEMM_SMEM>>>(yhi, ylo,
            wqkvw + (long)i * NPQKV * KPD,
            bqkv + i * NQKV, nullptr, qkvh, nullptr, nullptr, NTOK, NQKV, KPD, 0);
        attn_tc<<<dim3(HH, BB), 128>>>(qkvh, msk, ohi, olo);
        mma_gemm<2><<<dim3(4, 65), 256, GEMM_SMEM>>>(ohi, olo,
            woh + (long)i * NPD * KPD,
            bo + i * DD, h, h, nullptr, nullptr, NTOK, DD, KPD, 0);
        ln_split_w<0><<<(NTOK + 7) / 8, 256>>>(h, ln2g + i * DD, ln2b + i * DD,
                                               yhi, ylo, NTOK, DD, KPD);
        mma_gemm<1><<<dim3(8, 65), 256, GEMM_SMEM>>>(yhi, ylo,
            w1h + (long)i * NPH * KPD,
            b1 + i * HID, nullptr, nullptr, fhi, flo, NTOK, HID, KPD, KPH);
        mma_gemm<2><<<dim3(4, 65), 256, GEMM_SMEM>>>(fhi, flo,
            w2h + (long)i * NPD * KPH,
            b2 + i * DD, h, h, nullptr, nullptr, NTOK, DD, KPH, 0);
    }

    // ---- pool + head ----
    pool_kernel<<<BB, 256>>>(h, msk, pool);
    logits_kernel<<<BB, 256>>>(pool, logW, logb, out);
}